// round 5
// baseline (speedup 1.0000x reference)
#include <cuda_runtime.h>

#define G       4
#define NPTS    40000
#define K       64
#define D       400
#define TILE_N  128
#define DKC     16
#define NBLK    148
#define BPG     37          // blocks per group (NBLK/4)
#define TILES   313         // ceil(40000/128)
#define EPOCHS  10
#define AS_STR  132         // padded strides: avoid 32-way smem bank conflicts
#define BS_STR  68
#define SC_STR  65

// Scratch (allocation-free: __device__ globals)
__device__ float g_centroids[G * K * D];
__device__ float g_c2[G * K];
__device__ float g_slab[(size_t)NBLK * K * D];   // per-block partial sums (~15 MB)
__device__ int   g_slabcnt[NBLK * K];

__device__ __forceinline__ unsigned long long pack2f(float x, float y) {
    unsigned long long r;
    asm("mov.b64 %0, {%1, %2};" : "=l"(r) : "f"(x), "f"(y));
    return r;
}
__device__ __forceinline__ void unpack2f(unsigned long long v, float& x, float& y) {
    asm("mov.b64 {%0, %1}, %2;" : "=f"(x), "=f"(y) : "l"(v));
}
// Packed dual-lane IEEE FMA: 2x FFMA throughput on sm_103a, bitwise == scalar fmaf per lane.
__device__ __forceinline__ void fma2(unsigned long long& d, unsigned long long a, unsigned long long b) {
    asm("fma.rn.f32x2 %0, %1, %2, %0;" : "+l"(d) : "l"(a), "l"(b));
}

__device__ __forceinline__ float block_reduce_sum_128(float v) {
    __shared__ float ws[4];
    #pragma unroll
    for (int o = 16; o > 0; o >>= 1) v += __shfl_down_sync(0xffffffffu, v, o);
    if ((threadIdx.x & 31) == 0) ws[threadIdx.x >> 5] = v;
    __syncthreads();
    float r = 0.f;
    if (threadIdx.x == 0) r = ws[0] + ws[1] + ws[2] + ws[3];
    return r;
}

// Copy initial centroids into working buffer + compute 0.5*||c||^2
__global__ void init_kernel(const float* __restrict__ cinit) {
    const int b = blockIdx.x;          // g*K + k
    const int tid = threadIdx.x;       // 128 threads
    const float* src = cinit + (size_t)b * D;
    float s = 0.f;
    for (int d = tid; d < D; d += 128) {
        float v = src[d];
        g_centroids[(size_t)b * D + d] = v;
        s += v * v;
    }
    s = block_reduce_sum_128(s);
    if (tid == 0) g_c2[b] = 0.5f * s;
}

// The hot kernel: per-block (pinned to one group) over several 128-patch tiles:
//   scores GEMM (f32x2 packed FMA) -> argmax -> accumulate into private smem sums.
// Flush once to a per-block slab. No float atomics -> fully deterministic.
__global__ __launch_bounds__(256, 1)
void assign_kernel(const float* __restrict__ patches) {
    extern __shared__ float sm[];
    float* part   = sm;                          // K*D      partial sums (100KB)
    float* scores = part + K * D;                // TILE_N*SC_STR
    float* As     = scores + TILE_N * SC_STR;    // DKC*AS_STR  patch chunk (transposed)
    float* Bs     = As + DKC * AS_STR;           // DKC*BS_STR  centroid chunk (transposed)
    float* c2s    = Bs + DKC * BS_STR;           // K
    int*   labels = (int*)(c2s + K);             // TILE_N
    __shared__ int cnt[K];

    const int b   = blockIdx.x;
    const int g   = b & 3;
    const int bg  = b >> 2;
    const int tid = threadIdx.x;
    const int tx  = tid & 15;       // centroid micro-dim (16 x 4 = 64)
    const int ty  = tid >> 4;       // patch micro-dim   (16 x 8 = 128)
    const int lp  = tid >> 2;       // staging row 0..63
    const int lq  = tid & 3;        // staging quad 0..3

    for (int i = tid; i < K * D; i += 256) part[i] = 0.f;
    if (tid < K) { cnt[tid] = 0; c2s[tid] = g_c2[g * K + tid]; }
    __syncthreads();

    const float* Bsrc = g_centroids + (size_t)(g * K + lp) * D + lq * 4;

    for (int t = bg; t < TILES; t += BPG) {
        const int n0 = t * TILE_N;
        const int nrem = min(TILE_N, NPTS - n0);

        // acc[i][j]: packed pair of patches (ty*8+2i, ty*8+2i+1) vs centroid tx*4+j.
        // Init with -0.5*||c||^2 so argmax(scores) needs no epilogue subtract.
        unsigned long long acc[4][4];
        #pragma unroll
        for (int j = 0; j < 4; j++) {
            float nc = -c2s[tx * 4 + j];
            unsigned long long pv = pack2f(nc, nc);
            #pragma unroll
            for (int i = 0; i < 4; i++) acc[i][j] = pv;
        }

        const float* A0src = (lp < nrem)
            ? (patches + ((size_t)(n0 + lp) * G + g) * D + lq * 4) : (const float*)0;
        const float* A1src = (lp + 64 < nrem)
            ? (patches + ((size_t)(n0 + lp + 64) * G + g) * D + lq * 4) : (const float*)0;

        // register prefetch (hide DRAM latency under the FMA window)
        float4 ra0 = A0src ? *(const float4*)A0src : make_float4(0.f, 0.f, 0.f, 0.f);
        float4 ra1 = A1src ? *(const float4*)A1src : make_float4(0.f, 0.f, 0.f, 0.f);
        float4 rb  = *(const float4*)Bsrc;

        int off = DKC;
        #pragma unroll 1
        for (int c = 0; c < D / DKC; ++c) {
            __syncthreads();   // previous chunk's compute done; safe to overwrite As/Bs
            As[(lq * 4 + 0) * AS_STR + lp] = ra0.x;
            As[(lq * 4 + 1) * AS_STR + lp] = ra0.y;
            As[(lq * 4 + 2) * AS_STR + lp] = ra0.z;
            As[(lq * 4 + 3) * AS_STR + lp] = ra0.w;
            As[(lq * 4 + 0) * AS_STR + lp + 64] = ra1.x;
            As[(lq * 4 + 1) * AS_STR + lp + 64] = ra1.y;
            As[(lq * 4 + 2) * AS_STR + lp + 64] = ra1.z;
            As[(lq * 4 + 3) * AS_STR + lp + 64] = ra1.w;
            Bs[(lq * 4 + 0) * BS_STR + lp] = rb.x;
            Bs[(lq * 4 + 1) * BS_STR + lp] = rb.y;
            Bs[(lq * 4 + 2) * BS_STR + lp] = rb.z;
            Bs[(lq * 4 + 3) * BS_STR + lp] = rb.w;
            __syncthreads();
            if (c + 1 < D / DKC) {
                ra0 = A0src ? *(const float4*)(A0src + off) : make_float4(0.f, 0.f, 0.f, 0.f);
                ra1 = A1src ? *(const float4*)(A1src + off) : make_float4(0.f, 0.f, 0.f, 0.f);
                rb  = *(const float4*)(Bsrc + off);
                off += DKC;
            }
            #pragma unroll
            for (int kk = 0; kk < DKC; kk++) {
                const float4 a0 = *(const float4*)(As + kk * AS_STR + ty * 8);
                const float4 a1 = *(const float4*)(As + kk * AS_STR + ty * 8 + 4);
                const float4 bv = *(const float4*)(Bs + kk * BS_STR + tx * 4);
                unsigned long long ap[4], bd[4];
                ap[0] = pack2f(a0.x, a0.y);
                ap[1] = pack2f(a0.z, a0.w);
                ap[2] = pack2f(a1.x, a1.y);
                ap[3] = pack2f(a1.z, a1.w);
                bd[0] = pack2f(bv.x, bv.x);
                bd[1] = pack2f(bv.y, bv.y);
                bd[2] = pack2f(bv.z, bv.z);
                bd[3] = pack2f(bv.w, bv.w);
                #pragma unroll
                for (int i = 0; i < 4; i++)
                    #pragma unroll
                    for (int j = 0; j < 4; j++)
                        fma2(acc[i][j], ap[i], bd[j]);
            }
        }
        __syncthreads();

        // spill scores to smem (padded stride -> conflict-free argmax scan)
        #pragma unroll
        for (int i = 0; i < 4; i++) {
            #pragma unroll
            for (int j = 0; j < 4; j++) {
                float lo, hi;
                unpack2f(acc[i][j], lo, hi);
                scores[(ty * 8 + 2 * i    ) * SC_STR + tx * 4 + j] = lo;
                scores[(ty * 8 + 2 * i + 1) * SC_STR + tx * 4 + j] = hi;
            }
        }
        __syncthreads();

        // argmax (strict > keeps first index, matching jnp.argmax)
        if (tid < nrem) {
            const float* srow = scores + tid * SC_STR;
            float best = srow[0];
            int bi = 0;
            #pragma unroll
            for (int k = 1; k < K; k++) {
                float v = srow[k];
                if (v > best) { best = v; bi = k; }
            }
            labels[tid] = bi;
            atomicAdd(&cnt[bi], 1);   // integer shared atomic: deterministic
        }
        __syncthreads();

        // accumulate patches into private partial sums.
        // 2 patches per iteration with both global loads issued before the smem
        // RMWs -> doubled load MLP (latency-exposed phase, patch rows L2-hot).
        int p = 0;
        for (; p + 1 < nrem; p += 2) {
            const float* prow0 = patches + ((size_t)(n0 + p    ) * G + g) * D;
            const float* prow1 = patches + ((size_t)(n0 + p + 1) * G + g) * D;
            float v0a = prow0[tid];
            float v1a = prow1[tid];
            float v0b = 0.f, v1b = 0.f;
            if (tid < D - 256) { v0b = prow0[tid + 256]; v1b = prow1[tid + 256]; }
            float* dst0 = part + labels[p]     * D;
            float* dst1 = part + labels[p + 1] * D;
            dst0[tid] += v0a;
            if (tid < D - 256) dst0[tid + 256] += v0b;
            dst1[tid] += v1a;
            if (tid < D - 256) dst1[tid + 256] += v1b;
        }
        if (p < nrem) {
            const float* prow = patches + ((size_t)(n0 + p) * G + g) * D;
            float* dst = part + labels[p] * D;
            dst[tid] += prow[tid];
            if (tid < D - 256) dst[tid + 256] += prow[tid + 256];
        }
        __syncthreads();
    }

    for (int i = tid; i < K * D; i += 256) g_slab[(size_t)b * (K * D) + i] = part[i];
    if (tid < K) g_slabcnt[b * K + tid] = cnt[tid];
}

// Deterministic slab reduction + centroid update (+ empty-cluster rule) + next c2.
__global__ void update_kernel() {
    const int b = blockIdx.x;        // g*K + k
    const int g = b >> 6;
    const int k = b & 63;
    const int tid = threadIdx.x;     // 128 threads
    __shared__ int scnt[G];
    if (tid < G) {
        int c = 0;
        for (int j = 0; j < BPG; j++) c += g_slabcnt[(tid + 4 * j) * K + k];
        scnt[tid] = c;
    }
    __syncthreads();
    const bool bad = (scnt[0] == 0) | (scnt[1] == 0) | (scnt[2] == 0) | (scnt[3] == 0);
    const int cn = scnt[g];
    const float cf = (float)(cn == 0 ? 1 : cn);
    float ss = 0.f;
    for (int d = tid; d < D; d += 128) {
        float s = 0.f;
        for (int j = 0; j < BPG; j++)
            s += g_slab[(size_t)(g + 4 * j) * (K * D) + k * D + d];
        float v = bad ? 0.f : (s / cf);
        g_centroids[(size_t)b * D + d] = v;
        ss += v * v;
    }
    ss = block_reduce_sum_128(ss);
    if (tid == 0) g_c2[b] = 0.5f * ss;
}

__global__ void copy_out_kernel(float* __restrict__ out) {
    int i = blockIdx.x * 256 + threadIdx.x;
    if (i < G * K * D) out[i] = g_centroids[i];
}

extern "C" void kernel_launch(void* const* d_in, const int* in_sizes, int n_in,
                              void* d_out, int out_size) {
    const float* patches = (const float*)d_in[0];
    const float* cinit   = (const float*)d_in[1];
    if (n_in >= 2 && in_sizes[0] == G * K * D && in_sizes[1] != G * K * D) {
        patches = (const float*)d_in[1];
        cinit   = (const float*)d_in[0];
    }
    float* out = (float*)d_out;

    const int SMEM_BYTES =
        (K * D + TILE_N * SC_STR + DKC * AS_STR + DKC * BS_STR + K + TILE_N) * 4; // 149248
    cudaFuncSetAttribute(assign_kernel, cudaFuncAttributeMaxDynamicSharedMemorySize, SMEM_BYTES);

    init_kernel<<<G * K, 128>>>(cinit);
    for (int e = 0; e < EPOCHS; e++) {
        assign_kernel<<<NBLK, 256, SMEM_BYTES>>>(patches);
        update_kernel<<<G * K, 128>>>();
    }
    copy_out_kernel<<<(G * K * D + 255) / 256, 256>>>(out);
}